// round 1
// baseline (speedup 1.0000x reference)
#include <cuda_runtime.h>
#include <math.h>

#define T_SEQ   2048
#define D_MODEL 4096
#define NHEADS  32
#define KVHEADS 8
#define HDIM    128
#define WINDOW  1024

// ---------------- scratch (device globals; no allocation allowed) ----------------
__device__ float g_Wq[D_MODEL * (NHEADS * HDIM)];   // 64 MB: (D, N*H)
__device__ float g_Wk[D_MODEL * (KVHEADS * HDIM)];  // 16 MB: (D, K*H)
__device__ float g_Wv[D_MODEL * (KVHEADS * HDIM)];  // 16 MB
__device__ float g_Q [T_SEQ * NHEADS * HDIM];       // 32 MB: (T, N*H)
__device__ float g_K [T_SEQ * KVHEADS * HDIM];      // 8 MB
__device__ float g_V [T_SEQ * KVHEADS * HDIM];      // 8 MB
__device__ float g_Enc[T_SEQ * NHEADS * HDIM];      // 32 MB

// ---------------- weight repack ----------------
// q_w (N, D, H) -> Wq[d][n*H+h] ; kv_w (2, K, D, H) -> Wk/Wv[d][k*H+h]
__global__ void pack_weights(const float* __restrict__ qw, const float* __restrict__ kvw) {
    int stride = gridDim.x * blockDim.x;
    int tid = blockIdx.x * blockDim.x + threadIdx.x;
    const int TOTQ = D_MODEL * (NHEADS * HDIM);
    for (int i = tid; i < TOTQ; i += stride) {
        int d = i >> 12; int col = i & 4095; int n = col >> 7; int h = col & 127;
        g_Wq[i] = qw[((n * D_MODEL + d) << 7) + h];
    }
    const int TOTK = D_MODEL * (KVHEADS * HDIM);
    for (int i = tid; i < TOTK; i += stride) {
        int d = i >> 10; int col = i & 1023; int k = col >> 7; int h = col & 127;
        g_Wk[i] = kvw[((k * D_MODEL + d) << 7) + h];
        g_Wv[i] = kvw[(((KVHEADS + k) * D_MODEL + d) << 7) + h];
    }
}

// ---------------- tiled SGEMM: C(MxN) = A(MxK) * B(KxN), all row-major ----------------
__global__ __launch_bounds__(256)
void sgemm128(const float* __restrict__ A, const float* __restrict__ B,
              float* __restrict__ C, int M, int Nc, int Kd) {
    __shared__ __align__(16) float As[8][132];
    __shared__ __align__(16) float Bs[8][128];
    const int tid = threadIdx.x;
    const int bx = blockIdx.x, by = blockIdx.y;
    const float* Ab = A + (size_t)by * 128 * Kd;
    const float* Bb = B + bx * 128;
    const int arow = tid >> 1, acol = (tid & 1) << 2;
    const int brow = tid >> 5, bcol = (tid & 31) << 2;
    const int tx = tid & 15, ty = tid >> 4;
    float acc[8][8];
    #pragma unroll
    for (int i = 0; i < 8; i++)
        #pragma unroll
        for (int j = 0; j < 8; j++) acc[i][j] = 0.f;

    for (int k0 = 0; k0 < Kd; k0 += 8) {
        float4 av = *reinterpret_cast<const float4*>(Ab + (size_t)arow * Kd + k0 + acol);
        As[acol + 0][arow] = av.x;
        As[acol + 1][arow] = av.y;
        As[acol + 2][arow] = av.z;
        As[acol + 3][arow] = av.w;
        float4 bv = *reinterpret_cast<const float4*>(Bb + (size_t)(k0 + brow) * Nc + bcol);
        *reinterpret_cast<float4*>(&Bs[brow][bcol]) = bv;
        __syncthreads();
        #pragma unroll
        for (int kk = 0; kk < 8; kk++) {
            float ra[8], rb[8];
            *reinterpret_cast<float4*>(&ra[0]) = *reinterpret_cast<const float4*>(&As[kk][ty * 8]);
            *reinterpret_cast<float4*>(&ra[4]) = *reinterpret_cast<const float4*>(&As[kk][ty * 8 + 4]);
            *reinterpret_cast<float4*>(&rb[0]) = *reinterpret_cast<const float4*>(&Bs[kk][tx * 8]);
            *reinterpret_cast<float4*>(&rb[4]) = *reinterpret_cast<const float4*>(&Bs[kk][tx * 8 + 4]);
            #pragma unroll
            for (int i = 0; i < 8; i++)
                #pragma unroll
                for (int j = 0; j < 8; j++) acc[i][j] += ra[i] * rb[j];
        }
        __syncthreads();
    }
    float* Cb = C + (size_t)(by * 128) * Nc + bx * 128;
    #pragma unroll
    for (int i = 0; i < 8; i++) {
        float4 v0 = make_float4(acc[i][0], acc[i][1], acc[i][2], acc[i][3]);
        float4 v1 = make_float4(acc[i][4], acc[i][5], acc[i][6], acc[i][7]);
        *reinterpret_cast<float4*>(Cb + (size_t)(ty * 8 + i) * Nc + tx * 8) = v0;
        *reinterpret_cast<float4*>(Cb + (size_t)(ty * 8 + i) * Nc + tx * 8 + 4) = v1;
    }
}

// ---------------- RoPE (+ optional query scale) ----------------
__global__ void rope_kernel(float* __restrict__ data, const int* __restrict__ pos,
                            int n_heads, float scale) {
    int idx = blockIdx.x * blockDim.x + threadIdx.x;
    int total = T_SEQ * n_heads * 64;
    if (idx >= total) return;
    int hh = idx & 63;
    int nh = (idx >> 6) % n_heads;
    int t  = idx / (n_heads << 6);
    float ts  = powf(10000.0f, (float)hh * (1.0f / 64.0f));
    float ang = (float)pos[t] / ts;
    float sv = sinf(ang), cv = cosf(ang);
    float* row = data + (size_t)t * (n_heads * HDIM) + nh * HDIM;
    float a = row[hh], b = row[hh + 64];
    row[hh]      = (a * cv - b * sv) * scale;
    row[hh + 64] = (b * cv + a * sv) * scale;
}

// ---------------- flash-style attention with softcap + sliding window ----------------
// grid: (NHEADS, T_SEQ/64), 256 threads. Dynamic smem: Qs/Ks/Vs (64x129) + Ps (64x65).
__global__ __launch_bounds__(256)
void attn_kernel(const int* __restrict__ segpos) {
    extern __shared__ float sm[];
    float* Qs = sm;                    // 64*129
    float* Ks = Qs + 64 * 129;
    float* Vs = Ks + 64 * 129;
    float* Ps = Vs + 64 * 129;         // 64*65
    __shared__ int sp[64];

    const int n   = blockIdx.x;
    const int t0  = blockIdx.y * 64;
    const int kvh = n >> 2;
    const int tid = threadIdx.x;
    const int tx = tid & 15, ty = tid >> 4;

    for (int i = tid; i < 64 * 128; i += 256) {
        int r = i >> 7, c = i & 127;
        Qs[r * 129 + c] = g_Q[(size_t)(t0 + r) * (NHEADS * HDIM) + (n << 7) + c];
    }
    if (tid < 64) sp[tid] = segpos[t0 + tid];
    __syncthreads();

    float m[4], l[4], O[4][8];
    #pragma unroll
    for (int i = 0; i < 4; i++) {
        m[i] = -1e30f; l[i] = 0.f;
        #pragma unroll
        for (int j = 0; j < 8; j++) O[i][j] = 0.f;
    }

    int s_lo = sp[0] - (WINDOW - 1); if (s_lo < 0) s_lo = 0;
    int sb = s_lo & ~63;
    const int s_end = t0 + 63;

    for (int s0 = sb; s0 <= s_end; s0 += 64) {
        for (int i = tid; i < 64 * 128; i += 256) {
            int r = i >> 7, c = i & 127;
            size_t g = (size_t)(s0 + r) * (KVHEADS * HDIM) + (kvh << 7) + c;
            Ks[r * 129 + c] = g_K[g];
            Vs[r * 129 + c] = g_V[g];
        }
        __syncthreads();

        float sv[4][4];
        #pragma unroll
        for (int i = 0; i < 4; i++)
            #pragma unroll
            for (int j = 0; j < 4; j++) sv[i][j] = 0.f;

        #pragma unroll 8
        for (int kk = 0; kk < 128; kk++) {
            float qv[4], kv[4];
            #pragma unroll
            for (int i = 0; i < 4; i++) qv[i] = Qs[(ty * 4 + i) * 129 + kk];
            #pragma unroll
            for (int j = 0; j < 4; j++) kv[j] = Ks[(tx + 16 * j) * 129 + kk];
            #pragma unroll
            for (int i = 0; i < 4; i++)
                #pragma unroll
                for (int j = 0; j < 4; j++) sv[i][j] += qv[i] * kv[j];
        }

        // softcap + causal + sliding-window mask
        #pragma unroll
        for (int i = 0; i < 4; i++) {
            int r = t0 + ty * 4 + i;
            int p = sp[ty * 4 + i];
            #pragma unroll
            for (int j = 0; j < 4; j++) {
                int s = s0 + tx + 16 * j;
                float x = tanhf(sv[i][j] * (1.0f / 50.0f)) * 50.0f;
                bool ok = (s <= r) && (s > p - WINDOW) && (s < p + WINDOW);
                sv[i][j] = ok ? x : -1e30f;
            }
        }

        // online softmax (row reduction across tx within half-warp)
        #pragma unroll
        for (int i = 0; i < 4; i++) {
            float mx = fmaxf(fmaxf(sv[i][0], sv[i][1]), fmaxf(sv[i][2], sv[i][3]));
            #pragma unroll
            for (int off = 8; off > 0; off >>= 1)
                mx = fmaxf(mx, __shfl_xor_sync(0xffffffffu, mx, off, 16));
            float mnew  = fmaxf(m[i], mx);
            float alpha = expf(m[i] - mnew);
            float rs = 0.f;
            #pragma unroll
            for (int j = 0; j < 4; j++) {
                float pij = (sv[i][j] < -9e29f) ? 0.f : expf(sv[i][j] - mnew);
                sv[i][j] = pij;
                rs += pij;
            }
            #pragma unroll
            for (int off = 8; off > 0; off >>= 1)
                rs += __shfl_xor_sync(0xffffffffu, rs, off, 16);
            l[i] = l[i] * alpha + rs;
            #pragma unroll
            for (int j = 0; j < 8; j++) O[i][j] *= alpha;
            m[i] = mnew;
        }

        #pragma unroll
        for (int i = 0; i < 4; i++)
            #pragma unroll
            for (int j = 0; j < 4; j++)
                Ps[(ty * 4 + i) * 65 + tx + 16 * j] = sv[i][j];
        __syncthreads();

        // O += P @ V
        #pragma unroll 4
        for (int s = 0; s < 64; s++) {
            float pv[4], vv[8];
            #pragma unroll
            for (int i = 0; i < 4; i++) pv[i] = Ps[(ty * 4 + i) * 65 + s];
            #pragma unroll
            for (int j = 0; j < 8; j++) vv[j] = Vs[s * 129 + tx + 16 * j];
            #pragma unroll
            for (int i = 0; i < 4; i++)
                #pragma unroll
                for (int j = 0; j < 8; j++) O[i][j] += pv[i] * vv[j];
        }
        __syncthreads();
    }

    #pragma unroll
    for (int i = 0; i < 4; i++) {
        float inv = 1.0f / l[i];
        #pragma unroll
        for (int j = 0; j < 8; j++)
            g_Enc[(size_t)(t0 + ty * 4 + i) * (NHEADS * HDIM) + (n << 7) + tx + 16 * j] = O[i][j] * inv;
    }
}

// ---------------- launch ----------------
extern "C" void kernel_launch(void* const* d_in, const int* in_sizes, int n_in,
                              void* d_out, int out_size) {
    const float* x      = (const float*)d_in[0];   // (1, 2048, 4096)
    const int*   segpos = (const int*)d_in[1];     // (1, 2048)
    // d_in[2] = attn_mask (causal tril; combined analytically with sliding window)
    const float* qw   = (const float*)d_in[3];     // (32, 4096, 128)
    const float* kvw  = (const float*)d_in[4];     // (2, 8, 4096, 128)
    const float* outw = (const float*)d_in[5];     // (32, 128, 4096)
    float* out = (float*)d_out;                    // (1, 2048, 4096)

    float *pWq, *pWk, *pWv, *pQ, *pK, *pV, *pEnc;
    cudaGetSymbolAddress((void**)&pWq, g_Wq);
    cudaGetSymbolAddress((void**)&pWk, g_Wk);
    cudaGetSymbolAddress((void**)&pWv, g_Wv);
    cudaGetSymbolAddress((void**)&pQ,  g_Q);
    cudaGetSymbolAddress((void**)&pK,  g_K);
    cudaGetSymbolAddress((void**)&pV,  g_V);
    cudaGetSymbolAddress((void**)&pEnc, g_Enc);

    pack_weights<<<2048, 256>>>(qw, kvw);

    sgemm128<<<dim3(32, 16), 256>>>(x, pWq, pQ, T_SEQ, NHEADS * HDIM, D_MODEL);
    sgemm128<<<dim3(8, 16), 256>>>(x, pWk, pK, T_SEQ, KVHEADS * HDIM, D_MODEL);
    sgemm128<<<dim3(8, 16), 256>>>(x, pWv, pV, T_SEQ, KVHEADS * HDIM, D_MODEL);

    rope_kernel<<<(T_SEQ * NHEADS * 64 + 255) / 256, 256>>>(pQ, segpos, NHEADS, 0.08838834764831845f);
    rope_kernel<<<(T_SEQ * KVHEADS * 64 + 255) / 256, 256>>>(pK, segpos, KVHEADS, 1.0f);

    const int ATTN_SMEM = (3 * 64 * 129 + 64 * 65) * (int)sizeof(float);
    cudaFuncSetAttribute(attn_kernel, cudaFuncAttributeMaxDynamicSharedMemorySize, ATTN_SMEM);
    attn_kernel<<<dim3(NHEADS, T_SEQ / 64), 256, ATTN_SMEM>>>(segpos);

    sgemm128<<<dim3(32, 16), 256>>>(pEnc, outw, out, T_SEQ, D_MODEL, NHEADS * HDIM);
}

// round 2
// speedup vs baseline: 2.2810x; 2.2810x over previous
#include <cuda_runtime.h>
#include <cuda_bf16.h>
#include <math.h>
#include <stdint.h>

#define T_SEQ   2048
#define D_MODEL 4096
#define NHEADS  32
#define KVHEADS 8
#define HDIM    128
#define WINDOW  1024

// ---------------- scratch (device globals; no allocation allowed) ----------------
// bf16 hi/lo planes for tensor-core GEMMs
__device__ __nv_bfloat16 g_Ah[T_SEQ * D_MODEL];             // A plane (X, then Enc)
__device__ __nv_bfloat16 g_Al[T_SEQ * D_MODEL];
__device__ __nv_bfloat16 g_Bqh[D_MODEL * (NHEADS * HDIM)];  // (D, N*H)
__device__ __nv_bfloat16 g_Bql[D_MODEL * (NHEADS * HDIM)];
__device__ __nv_bfloat16 g_Bkh[D_MODEL * (KVHEADS * HDIM)];
__device__ __nv_bfloat16 g_Bkl[D_MODEL * (KVHEADS * HDIM)];
__device__ __nv_bfloat16 g_Bvh[D_MODEL * (KVHEADS * HDIM)];
__device__ __nv_bfloat16 g_Bvl[D_MODEL * (KVHEADS * HDIM)];
__device__ __nv_bfloat16 g_Boh[(NHEADS * HDIM) * D_MODEL];  // (N*H, D) straight
__device__ __nv_bfloat16 g_Bol[(NHEADS * HDIM) * D_MODEL];
// fp32 intermediates
__device__ float g_Q  [T_SEQ * NHEADS * HDIM];
__device__ float g_K  [T_SEQ * KVHEADS * HDIM];
__device__ float g_V  [T_SEQ * KVHEADS * HDIM];
__device__ float g_Enc[T_SEQ * NHEADS * HDIM];

// ---------------- helpers ----------------
__device__ __forceinline__ void split_bf16(float v, __nv_bfloat16& hi, __nv_bfloat16& lo) {
    hi = __float2bfloat16(v);
    lo = __float2bfloat16(v - __bfloat162float(hi));
}

__device__ __forceinline__ void cp16(void* dst, const void* src) {
    uint32_t d = (uint32_t)__cvta_generic_to_shared(dst);
    asm volatile("cp.async.cg.shared.global [%0], [%1], 16;\n" :: "r"(d), "l"(src));
}
__device__ __forceinline__ void cp_commit() { asm volatile("cp.async.commit_group;\n"); }

__device__ __forceinline__ void ldsm4(uint32_t& r0, uint32_t& r1, uint32_t& r2, uint32_t& r3,
                                      const __nv_bfloat16* p) {
    uint32_t a = (uint32_t)__cvta_generic_to_shared(p);
    asm volatile("ldmatrix.sync.aligned.m8n8.x4.shared.b16 {%0,%1,%2,%3}, [%4];"
                 : "=r"(r0), "=r"(r1), "=r"(r2), "=r"(r3) : "r"(a));
}
__device__ __forceinline__ void ldsm4t(uint32_t& r0, uint32_t& r1, uint32_t& r2, uint32_t& r3,
                                       const __nv_bfloat16* p) {
    uint32_t a = (uint32_t)__cvta_generic_to_shared(p);
    asm volatile("ldmatrix.sync.aligned.m8n8.x4.trans.shared.b16 {%0,%1,%2,%3}, [%4];"
                 : "=r"(r0), "=r"(r1), "=r"(r2), "=r"(r3) : "r"(a));
}
__device__ __forceinline__ void mma16816(float* c, const uint32_t* a, uint32_t b0, uint32_t b1) {
    asm volatile(
        "mma.sync.aligned.m16n8k16.row.col.f32.bf16.bf16.f32 "
        "{%0,%1,%2,%3}, {%4,%5,%6,%7}, {%8,%9}, {%0,%1,%2,%3};"
        : "+f"(c[0]), "+f"(c[1]), "+f"(c[2]), "+f"(c[3])
        : "r"(a[0]), "r"(a[1]), "r"(a[2]), "r"(a[3]), "r"(b0), "r"(b1));
}

// ---------------- convert / pack (fp32 -> bf16 hi/lo planes) ----------------
__global__ void pack_convert(const float* __restrict__ x, const float* __restrict__ qw,
                             const float* __restrict__ kvw, const float* __restrict__ ow) {
    int stride = gridDim.x * blockDim.x;
    int tid = blockIdx.x * blockDim.x + threadIdx.x;
    // X -> A planes
    const int NX = T_SEQ * D_MODEL;
    for (int i = tid; i < NX; i += stride) split_bf16(x[i], g_Ah[i], g_Al[i]);
    // q_w (N, D, H) -> Bq[d][n*H+h]
    const int NQ = D_MODEL * (NHEADS * HDIM);
    for (int i = tid; i < NQ; i += stride) {
        int d = i >> 12; int col = i & 4095; int n = col >> 7; int h = col & 127;
        split_bf16(qw[((n * D_MODEL + d) << 7) + h], g_Bqh[i], g_Bql[i]);
    }
    // kv_w (2, K, D, H) -> Bk/Bv[d][k*H+h]
    const int NK = D_MODEL * (KVHEADS * HDIM);
    for (int i = tid; i < NK; i += stride) {
        int d = i >> 10; int col = i & 1023; int k = col >> 7; int h = col & 127;
        split_bf16(kvw[((k * D_MODEL + d) << 7) + h], g_Bkh[i], g_Bkl[i]);
        split_bf16(kvw[(((KVHEADS + k) * D_MODEL + d) << 7) + h], g_Bvh[i], g_Bvl[i]);
    }
    // out_w (N, H, D) == (N*H, D) row-major: straight convert
    const int NO = (NHEADS * HDIM) * D_MODEL;
    for (int i = tid; i < NO; i += stride) split_bf16(ow[i], g_Boh[i], g_Bol[i]);
}

__global__ void enc_convert() {
    int stride = gridDim.x * blockDim.x;
    int tid = blockIdx.x * blockDim.x + threadIdx.x;
    const int N = T_SEQ * NHEADS * HDIM;
    for (int i = tid; i < N; i += stride) split_bf16(g_Enc[i], g_Ah[i], g_Al[i]);
}

// ---------------- bf16-split tensor-core GEMM ----------------
// C(M,N) = A(M,K) @ B(K,N); A,B given as bf16 hi/lo planes; C fp32.
// CTA tile 128x128, K-chunk 64, 2-stage cp.async pipeline, 8 warps (4x2), warp tile 32x64.
#define KC 64
#define SA 72          // A smem row stride (elems)
#define SB 136         // B smem row stride (elems)
#define OFF_AL (128 * SA)
#define OFF_BH (2 * 128 * SA)
#define OFF_BL (2 * 128 * SA + KC * SB)
#define STAGE_ELEMS (2 * 128 * SA + 2 * KC * SB)   // 35840 elems = 71680 B

__global__ __launch_bounds__(256)
void gemm_bf16split(const __nv_bfloat16* __restrict__ Ahg, const __nv_bfloat16* __restrict__ Alg,
                    const __nv_bfloat16* __restrict__ Bhg, const __nv_bfloat16* __restrict__ Blg,
                    float* __restrict__ C, int M, int Nc, int Kd) {
    extern __shared__ __nv_bfloat16 smem[];
    const int tid  = threadIdx.x;
    const int lane = tid & 31;
    const int wid  = tid >> 5;
    const int wm   = wid >> 1;     // 0..3
    const int wn   = wid & 1;      // 0..1
    const int bx = blockIdx.x, by = blockIdx.y;
    const int row0 = by * 128;
    const int n0   = bx * 128;

    const int lrow = lane & 15;
    const int lcol = (lane >> 4) << 3;

    float acc[2][8][4];
    #pragma unroll
    for (int mt = 0; mt < 2; mt++)
        #pragma unroll
        for (int nt = 0; nt < 8; nt++)
            #pragma unroll
            for (int r = 0; r < 4; r++) acc[mt][nt][r] = 0.f;

    const int KT = Kd >> 6;

    // stage copy lambda-ish macro via function scope
    auto stage_copy = [&](int buf, int k0) {
        __nv_bfloat16* s = smem + buf * STAGE_ELEMS;
        #pragma unroll
        for (int c = tid; c < 1024; c += 256) {
            int r = c >> 3, col = (c & 7) << 3;
            size_t g = (size_t)(row0 + r) * Kd + k0 + col;
            cp16(s + r * SA + col, Ahg + g);
            cp16(s + OFF_AL + r * SA + col, Alg + g);
        }
        #pragma unroll
        for (int c = tid; c < 1024; c += 256) {
            int r = c >> 4, col = (c & 15) << 3;
            size_t g = (size_t)(k0 + r) * Nc + n0 + col;
            cp16(s + OFF_BH + r * SB + col, Bhg + g);
            cp16(s + OFF_BL + r * SB + col, Blg + g);
        }
    };

    stage_copy(0, 0);
    cp_commit();

    for (int kt = 0; kt < KT; kt++) {
        if (kt + 1 < KT) {
            stage_copy((kt + 1) & 1, (kt + 1) << 6);
            cp_commit();
            asm volatile("cp.async.wait_group 1;\n");
        } else {
            asm volatile("cp.async.wait_group 0;\n");
        }
        __syncthreads();

        const __nv_bfloat16* s  = smem + (kt & 1) * STAGE_ELEMS;
        const __nv_bfloat16* Ah = s;
        const __nv_bfloat16* Al = s + OFF_AL;
        const __nv_bfloat16* Bh = s + OFF_BH;
        const __nv_bfloat16* Bl = s + OFF_BL;

        #pragma unroll
        for (int k16 = 0; k16 < 4; k16++) {
            const int kc = k16 << 4;
            uint32_t ah[2][4], al[2][4];
            #pragma unroll
            for (int mt = 0; mt < 2; mt++) {
                const __nv_bfloat16* pa = Ah + (wm * 32 + mt * 16 + lrow) * SA + kc + lcol;
                ldsm4(ah[mt][0], ah[mt][1], ah[mt][2], ah[mt][3], pa);
                const __nv_bfloat16* pl = Al + (wm * 32 + mt * 16 + lrow) * SA + kc + lcol;
                ldsm4(al[mt][0], al[mt][1], al[mt][2], al[mt][3], pl);
            }
            #pragma unroll
            for (int j = 0; j < 4; j++) {
                uint32_t bh[4], bl[4];
                const __nv_bfloat16* pb = Bh + (kc + lrow) * SB + wn * 64 + j * 16 + lcol;
                ldsm4t(bh[0], bh[1], bh[2], bh[3], pb);
                const __nv_bfloat16* pbl = Bl + (kc + lrow) * SB + wn * 64 + j * 16 + lcol;
                ldsm4t(bl[0], bl[1], bl[2], bl[3], pbl);
                #pragma unroll
                for (int mt = 0; mt < 2; mt++) {
                    mma16816(acc[mt][2 * j],     ah[mt], bh[0], bh[1]);
                    mma16816(acc[mt][2 * j],     ah[mt], bl[0], bl[1]);
                    mma16816(acc[mt][2 * j],     al[mt], bh[0], bh[1]);
                    mma16816(acc[mt][2 * j + 1], ah[mt], bh[2], bh[3]);
                    mma16816(acc[mt][2 * j + 1], ah[mt], bl[2], bl[3]);
                    mma16816(acc[mt][2 * j + 1], al[mt], bh[2], bh[3]);
                }
            }
        }
        __syncthreads();
    }

    // epilogue
    float* Cb = C + (size_t)(row0 + wm * 32) * Nc + n0 + wn * 64;
    const int g  = lane >> 2;
    const int tc = (lane & 3) * 2;
    #pragma unroll
    for (int mt = 0; mt < 2; mt++)
        #pragma unroll
        for (int nt = 0; nt < 8; nt++) {
            float2 v0 = make_float2(acc[mt][nt][0], acc[mt][nt][1]);
            float2 v1 = make_float2(acc[mt][nt][2], acc[mt][nt][3]);
            *reinterpret_cast<float2*>(Cb + (size_t)(mt * 16 + g) * Nc + nt * 8 + tc)     = v0;
            *reinterpret_cast<float2*>(Cb + (size_t)(mt * 16 + g + 8) * Nc + nt * 8 + tc) = v1;
        }
}

// ---------------- RoPE (+ optional query scale) ----------------
__global__ void rope_kernel(float* __restrict__ data, const int* __restrict__ pos,
                            int n_heads, float scale) {
    int idx = blockIdx.x * blockDim.x + threadIdx.x;
    int total = T_SEQ * n_heads * 64;
    if (idx >= total) return;
    int hh = idx & 63;
    int nh = (idx >> 6) % n_heads;
    int t  = idx / (n_heads << 6);
    float ts  = powf(10000.0f, (float)hh * (1.0f / 64.0f));
    float ang = (float)pos[t] / ts;
    float sv = sinf(ang), cv = cosf(ang);
    float* row = data + (size_t)t * (n_heads * HDIM) + nh * HDIM;
    float a = row[hh], b = row[hh + 64];
    row[hh]      = (a * cv - b * sv) * scale;
    row[hh + 64] = (b * cv + a * sv) * scale;
}

// ---------------- flash-style attention with softcap + sliding window ----------------
__global__ __launch_bounds__(256)
void attn_kernel(const int* __restrict__ segpos) {
    extern __shared__ float sm[];
    float* Qs = sm;                    // 64*129
    float* Ks = Qs + 64 * 129;
    float* Vs = Ks + 64 * 129;
    float* Ps = Vs + 64 * 129;         // 64*65
    __shared__ int sp[64];

    const int n   = blockIdx.x;
    const int t0  = blockIdx.y * 64;
    const int kvh = n >> 2;
    const int tid = threadIdx.x;
    const int tx = tid & 15, ty = tid >> 4;

    for (int i = tid; i < 64 * 128; i += 256) {
        int r = i >> 7, c = i & 127;
        Qs[r * 129 + c] = g_Q[(size_t)(t0 + r) * (NHEADS * HDIM) + (n << 7) + c];
    }
    if (tid < 64) sp[tid] = segpos[t0 + tid];
    __syncthreads();

    float m[4], l[4], O[4][8];
    #pragma unroll
    for (int i = 0; i < 4; i++) {
        m[i] = -1e30f; l[i] = 0.f;
        #pragma unroll
        for (int j = 0; j < 8; j++) O[i][j] = 0.f;
    }

    int s_lo = sp[0] - (WINDOW - 1); if (s_lo < 0) s_lo = 0;
    int sb = s_lo & ~63;
    const int s_end = t0 + 63;

    for (int s0 = sb; s0 <= s_end; s0 += 64) {
        for (int i = tid; i < 64 * 128; i += 256) {
            int r = i >> 7, c = i & 127;
            size_t g = (size_t)(s0 + r) * (KVHEADS * HDIM) + (kvh << 7) + c;
            Ks[r * 129 + c] = g_K[g];
            Vs[r * 129 + c] = g_V[g];
        }
        __syncthreads();

        float sv[4][4];
        #pragma unroll
        for (int i = 0; i < 4; i++)
            #pragma unroll
            for (int j = 0; j < 4; j++) sv[i][j] = 0.f;

        #pragma unroll 8
        for (int kk = 0; kk < 128; kk++) {
            float qv[4], kv[4];
            #pragma unroll
            for (int i = 0; i < 4; i++) qv[i] = Qs[(ty * 4 + i) * 129 + kk];
            #pragma unroll
            for (int j = 0; j < 4; j++) kv[j] = Ks[(tx + 16 * j) * 129 + kk];
            #pragma unroll
            for (int i = 0; i < 4; i++)
                #pragma unroll
                for (int j = 0; j < 4; j++) sv[i][j] += qv[i] * kv[j];
        }

        #pragma unroll
        for (int i = 0; i < 4; i++) {
            int r = t0 + ty * 4 + i;
            int p = sp[ty * 4 + i];
            #pragma unroll
            for (int j = 0; j < 4; j++) {
                int s = s0 + tx + 16 * j;
                float x = tanhf(sv[i][j] * (1.0f / 50.0f)) * 50.0f;
                bool ok = (s <= r) && (s > p - WINDOW) && (s < p + WINDOW);
                sv[i][j] = ok ? x : -1e30f;
            }
        }

        #pragma unroll
        for (int i = 0; i < 4; i++) {
            float mx = fmaxf(fmaxf(sv[i][0], sv[i][1]), fmaxf(sv[i][2], sv[i][3]));
            #pragma unroll
            for (int off = 8; off > 0; off >>= 1)
                mx = fmaxf(mx, __shfl_xor_sync(0xffffffffu, mx, off, 16));
            float mnew  = fmaxf(m[i], mx);
            float alpha = expf(m[i] - mnew);
            float rs = 0.f;
            #pragma unroll
            for (int j = 0; j < 4; j++) {
                float pij = (sv[i][j] < -9e29f) ? 0.f : expf(sv[i][j] - mnew);
                sv[i][j] = pij;
                rs += pij;
            }
            #pragma unroll
            for (int off = 8; off > 0; off >>= 1)
                rs += __shfl_xor_sync(0xffffffffu, rs, off, 16);
            l[i] = l[i] * alpha + rs;
            #pragma unroll
            for (int j = 0; j < 8; j++) O[i][j] *= alpha;
            m[i] = mnew;
        }

        #pragma unroll
        for (int i = 0; i < 4; i++)
            #pragma unroll
            for (int j = 0; j < 4; j++)
                Ps[(ty * 4 + i) * 65 + tx + 16 * j] = sv[i][j];
        __syncthreads();

        #pragma unroll 4
        for (int s = 0; s < 64; s++) {
            float pv[4], vv[8];
            #pragma unroll
            for (int i = 0; i < 4; i++) pv[i] = Ps[(ty * 4 + i) * 65 + s];
            #pragma unroll
            for (int j = 0; j < 8; j++) vv[j] = Vs[s * 129 + tx + 16 * j];
            #pragma unroll
            for (int i = 0; i < 4; i++)
                #pragma unroll
                for (int j = 0; j < 8; j++) O[i][j] += pv[i] * vv[j];
        }
        __syncthreads();
    }

    #pragma unroll
    for (int i = 0; i < 4; i++) {
        float inv = 1.0f / l[i];
        #pragma unroll
        for (int j = 0; j < 8; j++)
            g_Enc[(size_t)(t0 + ty * 4 + i) * (NHEADS * HDIM) + (n << 7) + tx + 16 * j] = O[i][j] * inv;
    }
}

// ---------------- launch ----------------
extern "C" void kernel_launch(void* const* d_in, const int* in_sizes, int n_in,
                              void* d_out, int out_size) {
    const float* x      = (const float*)d_in[0];   // (1, 2048, 4096)
    const int*   segpos = (const int*)d_in[1];     // (1, 2048)
    const float* qw   = (const float*)d_in[3];     // (32, 4096, 128)
    const float* kvw  = (const float*)d_in[4];     // (2, 8, 4096, 128)
    const float* outw = (const float*)d_in[5];     // (32, 128, 4096)
    float* out = (float*)d_out;                    // (1, 2048, 4096)

    __nv_bfloat16 *pAh, *pAl, *pBqh, *pBql, *pBkh, *pBkl, *pBvh, *pBvl, *pBoh, *pBol;
    float *pQ, *pK, *pV, *pEnc;
    cudaGetSymbolAddress((void**)&pAh, g_Ah);
    cudaGetSymbolAddress((void**)&pAl, g_Al);
    cudaGetSymbolAddress((void**)&pBqh, g_Bqh);
    cudaGetSymbolAddress((void**)&pBql, g_Bql);
    cudaGetSymbolAddress((void**)&pBkh, g_Bkh);
    cudaGetSymbolAddress((void**)&pBkl, g_Bkl);
    cudaGetSymbolAddress((void**)&pBvh, g_Bvh);
    cudaGetSymbolAddress((void**)&pBvl, g_Bvl);
    cudaGetSymbolAddress((void**)&pBoh, g_Boh);
    cudaGetSymbolAddress((void**)&pBol, g_Bol);
    cudaGetSymbolAddress((void**)&pQ,  g_Q);
    cudaGetSymbolAddress((void**)&pK,  g_K);
    cudaGetSymbolAddress((void**)&pV,  g_V);
    cudaGetSymbolAddress((void**)&pEnc, g_Enc);

    pack_convert<<<2048, 256>>>(x, qw, kvw, outw);

    const int GEMM_SMEM = 2 * STAGE_ELEMS * (int)sizeof(__nv_bfloat16);  // 143360
    cudaFuncSetAttribute(gemm_bf16split, cudaFuncAttributeMaxDynamicSharedMemorySize, GEMM_SMEM);

    gemm_bf16split<<<dim3(32, 16), 256, GEMM_SMEM>>>(pAh, pAl, pBqh, pBql, pQ, T_SEQ, NHEADS * HDIM, D_MODEL);
    gemm_bf16split<<<dim3(8, 16), 256, GEMM_SMEM>>>(pAh, pAl, pBkh, pBkl, pK, T_SEQ, KVHEADS * HDIM, D_MODEL);
    gemm_bf16split<<<dim3(8, 16), 256, GEMM_SMEM>>>(pAh, pAl, pBvh, pBvl, pV, T_SEQ, KVHEADS * HDIM, D_MODEL);

    rope_kernel<<<(T_SEQ * NHEADS * 64 + 255) / 256, 256>>>(pQ, segpos, NHEADS, 0.08838834764831845f);
    rope_kernel<<<(T_SEQ * KVHEADS * 64 + 255) / 256, 256>>>(pK, segpos, KVHEADS, 1.0f);

    const int ATTN_SMEM = (3 * 64 * 129 + 64 * 65) * (int)sizeof(float);
    cudaFuncSetAttribute(attn_kernel, cudaFuncAttributeMaxDynamicSharedMemorySize, ATTN_SMEM);
    attn_kernel<<<dim3(NHEADS, T_SEQ / 64), 256, ATTN_SMEM>>>(segpos);

    enc_convert<<<2048, 256>>>();

    gemm_bf16split<<<dim3(32, 16), 256, GEMM_SMEM>>>(pAh, pAl, pBoh, pBol, out, T_SEQ, D_MODEL, NHEADS * HDIM);
}

// round 3
// speedup vs baseline: 3.4522x; 1.5135x over previous
#include <cuda_runtime.h>
#include <cuda_bf16.h>
#include <math.h>
#include <stdint.h>

#define T_SEQ   2048
#define D_MODEL 4096
#define NHEADS  32
#define KVHEADS 8
#define HDIM    128
#define WINDOW  1024

// ---------------- scratch (device globals; no allocation allowed) ----------------
__device__ __nv_bfloat16 g_Ah[T_SEQ * D_MODEL];             // A plane (X, then Enc)
__device__ __nv_bfloat16 g_Al[T_SEQ * D_MODEL];
__device__ __nv_bfloat16 g_Bqh[D_MODEL * (NHEADS * HDIM)];  // (D, N*H)
__device__ __nv_bfloat16 g_Bql[D_MODEL * (NHEADS * HDIM)];
__device__ __nv_bfloat16 g_Bkh[D_MODEL * (KVHEADS * HDIM)];
__device__ __nv_bfloat16 g_Bkl[D_MODEL * (KVHEADS * HDIM)];
__device__ __nv_bfloat16 g_Bvh[D_MODEL * (KVHEADS * HDIM)];
__device__ __nv_bfloat16 g_Bvl[D_MODEL * (KVHEADS * HDIM)];
__device__ __nv_bfloat16 g_Boh[(NHEADS * HDIM) * D_MODEL];  // (N*H, D)
__device__ __nv_bfloat16 g_Bol[(NHEADS * HDIM) * D_MODEL];
// fp32 intermediates from projections
__device__ float g_Q  [T_SEQ * NHEADS * HDIM];
__device__ float g_K  [T_SEQ * KVHEADS * HDIM];
__device__ float g_V  [T_SEQ * KVHEADS * HDIM];
__device__ float g_Enc[T_SEQ * NHEADS * HDIM];
// bf16 hi/lo planes for attention (post-RoPE)
__device__ __nv_bfloat16 g_Qh[T_SEQ * NHEADS * HDIM];
__device__ __nv_bfloat16 g_Ql2[T_SEQ * NHEADS * HDIM];
__device__ __nv_bfloat16 g_Kh[T_SEQ * KVHEADS * HDIM];
__device__ __nv_bfloat16 g_Kl[T_SEQ * KVHEADS * HDIM];
__device__ __nv_bfloat16 g_Vh[T_SEQ * KVHEADS * HDIM];
__device__ __nv_bfloat16 g_Vl[T_SEQ * KVHEADS * HDIM];

// ---------------- helpers ----------------
__device__ __forceinline__ void split_bf16(float v, __nv_bfloat16& hi, __nv_bfloat16& lo) {
    hi = __float2bfloat16(v);
    lo = __float2bfloat16(v - __bfloat162float(hi));
}

__device__ __forceinline__ void cp16(void* dst, const void* src) {
    uint32_t d = (uint32_t)__cvta_generic_to_shared(dst);
    asm volatile("cp.async.cg.shared.global [%0], [%1], 16;\n" :: "r"(d), "l"(src));
}
__device__ __forceinline__ void cp_commit() { asm volatile("cp.async.commit_group;\n"); }

__device__ __forceinline__ void ldsm4(uint32_t& r0, uint32_t& r1, uint32_t& r2, uint32_t& r3,
                                      const __nv_bfloat16* p) {
    uint32_t a = (uint32_t)__cvta_generic_to_shared(p);
    asm volatile("ldmatrix.sync.aligned.m8n8.x4.shared.b16 {%0,%1,%2,%3}, [%4];"
                 : "=r"(r0), "=r"(r1), "=r"(r2), "=r"(r3) : "r"(a));
}
__device__ __forceinline__ void ldsm4t(uint32_t& r0, uint32_t& r1, uint32_t& r2, uint32_t& r3,
                                       const __nv_bfloat16* p) {
    uint32_t a = (uint32_t)__cvta_generic_to_shared(p);
    asm volatile("ldmatrix.sync.aligned.m8n8.x4.trans.shared.b16 {%0,%1,%2,%3}, [%4];"
                 : "=r"(r0), "=r"(r1), "=r"(r2), "=r"(r3) : "r"(a));
}
__device__ __forceinline__ void mma16816(float* c, const uint32_t* a, uint32_t b0, uint32_t b1) {
    asm volatile(
        "mma.sync.aligned.m16n8k16.row.col.f32.bf16.bf16.f32 "
        "{%0,%1,%2,%3}, {%4,%5,%6,%7}, {%8,%9}, {%0,%1,%2,%3};"
        : "+f"(c[0]), "+f"(c[1]), "+f"(c[2]), "+f"(c[3])
        : "r"(a[0]), "r"(a[1]), "r"(a[2]), "r"(a[3]), "r"(b0), "r"(b1));
}
__device__ __forceinline__ void pack_split(float a, float b, uint32_t& hi, uint32_t& lo) {
    __nv_bfloat16 ha = __float2bfloat16(a);
    __nv_bfloat16 hb = __float2bfloat16(b);
    float ra = a - __bfloat162float(ha);
    float rb = b - __bfloat162float(hb);
    __nv_bfloat162 h2 = __halves2bfloat162(ha, hb);
    __nv_bfloat162 l2 = __halves2bfloat162(__float2bfloat16(ra), __float2bfloat16(rb));
    hi = *reinterpret_cast<uint32_t*>(&h2);
    lo = *reinterpret_cast<uint32_t*>(&l2);
}

// ---------------- convert / pack (fp32 -> bf16 hi/lo planes) ----------------
__global__ void pack_convert(const float* __restrict__ x, const float* __restrict__ qw,
                             const float* __restrict__ kvw, const float* __restrict__ ow) {
    int stride = gridDim.x * blockDim.x;
    int tid = blockIdx.x * blockDim.x + threadIdx.x;
    const int NX = T_SEQ * D_MODEL;
    for (int i = tid; i < NX; i += stride) split_bf16(x[i], g_Ah[i], g_Al[i]);
    const int NQ = D_MODEL * (NHEADS * HDIM);
    for (int i = tid; i < NQ; i += stride) {
        int d = i >> 12; int col = i & 4095; int n = col >> 7; int h = col & 127;
        split_bf16(qw[((n * D_MODEL + d) << 7) + h], g_Bqh[i], g_Bql[i]);
    }
    const int NK = D_MODEL * (KVHEADS * HDIM);
    for (int i = tid; i < NK; i += stride) {
        int d = i >> 10; int col = i & 1023; int k = col >> 7; int h = col & 127;
        split_bf16(kvw[((k * D_MODEL + d) << 7) + h], g_Bkh[i], g_Bkl[i]);
        split_bf16(kvw[(((KVHEADS + k) * D_MODEL + d) << 7) + h], g_Bvh[i], g_Bvl[i]);
    }
    const int NO = (NHEADS * HDIM) * D_MODEL;
    for (int i = tid; i < NO; i += stride) split_bf16(ow[i], g_Boh[i], g_Bol[i]);
}

__global__ void enc_convert() {
    int stride = gridDim.x * blockDim.x;
    int tid = blockIdx.x * blockDim.x + threadIdx.x;
    const int N = T_SEQ * NHEADS * HDIM;
    for (int i = tid; i < N; i += stride) split_bf16(g_Enc[i], g_Ah[i], g_Al[i]);
}

// ---------------- bf16-split tensor-core GEMM (same as R2) ----------------
#define KC 64
#define SA 72
#define SB 136
#define OFF_AL (128 * SA)
#define OFF_BH (2 * 128 * SA)
#define OFF_BL (2 * 128 * SA + KC * SB)
#define STAGE_ELEMS (2 * 128 * SA + 2 * KC * SB)

__global__ __launch_bounds__(256)
void gemm_bf16split(const __nv_bfloat16* __restrict__ Ahg, const __nv_bfloat16* __restrict__ Alg,
                    const __nv_bfloat16* __restrict__ Bhg, const __nv_bfloat16* __restrict__ Blg,
                    float* __restrict__ C, int M, int Nc, int Kd) {
    extern __shared__ __nv_bfloat16 smem[];
    const int tid  = threadIdx.x;
    const int lane = tid & 31;
    const int wid  = tid >> 5;
    const int wm   = wid >> 1;
    const int wn   = wid & 1;
    const int bx = blockIdx.x, by = blockIdx.y;
    const int row0 = by * 128;
    const int n0   = bx * 128;
    const int lrow = lane & 15;
    const int lcol = (lane >> 4) << 3;

    float acc[2][8][4];
    #pragma unroll
    for (int mt = 0; mt < 2; mt++)
        #pragma unroll
        for (int nt = 0; nt < 8; nt++)
            #pragma unroll
            for (int r = 0; r < 4; r++) acc[mt][nt][r] = 0.f;

    const int KT = Kd >> 6;

    auto stage_copy = [&](int buf, int k0) {
        __nv_bfloat16* s = smem + buf * STAGE_ELEMS;
        #pragma unroll
        for (int c = tid; c < 1024; c += 256) {
            int r = c >> 3, col = (c & 7) << 3;
            size_t g = (size_t)(row0 + r) * Kd + k0 + col;
            cp16(s + r * SA + col, Ahg + g);
            cp16(s + OFF_AL + r * SA + col, Alg + g);
        }
        #pragma unroll
        for (int c = tid; c < 1024; c += 256) {
            int r = c >> 4, col = (c & 15) << 3;
            size_t g = (size_t)(k0 + r) * Nc + n0 + col;
            cp16(s + OFF_BH + r * SB + col, Bhg + g);
            cp16(s + OFF_BL + r * SB + col, Blg + g);
        }
    };

    stage_copy(0, 0);
    cp_commit();

    for (int kt = 0; kt < KT; kt++) {
        if (kt + 1 < KT) {
            stage_copy((kt + 1) & 1, (kt + 1) << 6);
            cp_commit();
            asm volatile("cp.async.wait_group 1;\n");
        } else {
            asm volatile("cp.async.wait_group 0;\n");
        }
        __syncthreads();

        const __nv_bfloat16* s  = smem + (kt & 1) * STAGE_ELEMS;
        const __nv_bfloat16* Ah = s;
        const __nv_bfloat16* Al = s + OFF_AL;
        const __nv_bfloat16* Bh = s + OFF_BH;
        const __nv_bfloat16* Bl = s + OFF_BL;

        #pragma unroll
        for (int k16 = 0; k16 < 4; k16++) {
            const int kc = k16 << 4;
            uint32_t ah[2][4], al[2][4];
            #pragma unroll
            for (int mt = 0; mt < 2; mt++) {
                const __nv_bfloat16* pa = Ah + (wm * 32 + mt * 16 + lrow) * SA + kc + lcol;
                ldsm4(ah[mt][0], ah[mt][1], ah[mt][2], ah[mt][3], pa);
                const __nv_bfloat16* pl = Al + (wm * 32 + mt * 16 + lrow) * SA + kc + lcol;
                ldsm4(al[mt][0], al[mt][1], al[mt][2], al[mt][3], pl);
            }
            #pragma unroll
            for (int j = 0; j < 4; j++) {
                uint32_t bh[4], bl[4];
                const __nv_bfloat16* pb = Bh + (kc + lrow) * SB + wn * 64 + j * 16 + lcol;
                ldsm4t(bh[0], bh[1], bh[2], bh[3], pb);
                const __nv_bfloat16* pbl = Bl + (kc + lrow) * SB + wn * 64 + j * 16 + lcol;
                ldsm4t(bl[0], bl[1], bl[2], bl[3], pbl);
                #pragma unroll
                for (int mt = 0; mt < 2; mt++) {
                    mma16816(acc[mt][2 * j],     ah[mt], bh[0], bh[1]);
                    mma16816(acc[mt][2 * j],     ah[mt], bl[0], bl[1]);
                    mma16816(acc[mt][2 * j],     al[mt], bh[0], bh[1]);
                    mma16816(acc[mt][2 * j + 1], ah[mt], bh[2], bh[3]);
                    mma16816(acc[mt][2 * j + 1], ah[mt], bl[2], bl[3]);
                    mma16816(acc[mt][2 * j + 1], al[mt], bh[2], bh[3]);
                }
            }
        }
        __syncthreads();
    }

    float* Cb = C + (size_t)(row0 + wm * 32) * Nc + n0 + wn * 64;
    const int g  = lane >> 2;
    const int tc = (lane & 3) * 2;
    #pragma unroll
    for (int mt = 0; mt < 2; mt++)
        #pragma unroll
        for (int nt = 0; nt < 8; nt++) {
            float2 v0 = make_float2(acc[mt][nt][0], acc[mt][nt][1]);
            float2 v1 = make_float2(acc[mt][nt][2], acc[mt][nt][3]);
            *reinterpret_cast<float2*>(Cb + (size_t)(mt * 16 + g) * Nc + nt * 8 + tc)     = v0;
            *reinterpret_cast<float2*>(Cb + (size_t)(mt * 16 + g + 8) * Nc + nt * 8 + tc) = v1;
        }
}

// ---------------- fused RoPE + scale + bf16 hi/lo split ----------------
__global__ void rope_split(const float* __restrict__ src, const int* __restrict__ pos,
                           int n_heads, float scale,
                           __nv_bfloat16* __restrict__ dh, __nv_bfloat16* __restrict__ dl) {
    int idx = blockIdx.x * blockDim.x + threadIdx.x;
    int total = T_SEQ * n_heads * 64;
    if (idx >= total) return;
    int hh = idx & 63;
    int nh = (idx >> 6) % n_heads;
    int t  = idx / (n_heads << 6);
    float ts  = powf(10000.0f, (float)hh * (1.0f / 64.0f));
    float ang = (float)pos[t] / ts;
    float sv = sinf(ang), cv = cosf(ang);
    size_t base = (size_t)t * (n_heads * HDIM) + nh * HDIM;
    float a = src[base + hh], b = src[base + hh + 64];
    float o1 = (a * cv - b * sv) * scale;
    float o2 = (b * cv + a * sv) * scale;
    split_bf16(o1, dh[base + hh], dl[base + hh]);
    split_bf16(o2, dh[base + hh + 64], dl[base + hh + 64]);
}

__global__ void v_split() {
    int stride = gridDim.x * blockDim.x;
    int tid = blockIdx.x * blockDim.x + threadIdx.x;
    const int N = T_SEQ * KVHEADS * HDIM;
    for (int i = tid; i < N; i += stride) split_bf16(g_V[i], g_Vh[i], g_Vl[i]);
}

// ---------------- tensor-core flash attention ----------------
#define AST 136   // smem row stride (bf16 elems): 272B -> conflict-free ldmatrix

__global__ __launch_bounds__(128, 2)
void attn_tc(const int* __restrict__ segpos) {
    extern __shared__ __nv_bfloat16 dsm[];
    __nv_bfloat16* Qh = dsm;
    __nv_bfloat16* Ql = Qh + 64 * AST;
    __nv_bfloat16* Kh = Ql + 64 * AST;
    __nv_bfloat16* Kl = Kh + 64 * AST;
    __nv_bfloat16* Vh = Kl + 64 * AST;
    __nv_bfloat16* Vl = Vh + 64 * AST;
    __shared__ int sp[64];

    const int n   = blockIdx.x;
    const int t0  = blockIdx.y * 64;
    const int kvh = n >> 2;
    const int tid = threadIdx.x;
    const int lane = tid & 31;
    const int w = tid >> 5;

    // load Q tile (hi/lo)
    #pragma unroll
    for (int i = tid; i < 1024; i += 128) {
        int r = i >> 4, c = (i & 15) << 3;
        size_t g = (size_t)(t0 + r) * (NHEADS * HDIM) + (n << 7) + c;
        cp16(Qh + r * AST + c, g_Qh + g);
        cp16(Ql + r * AST + c, g_Ql2 + g);
    }
    if (tid < 64) sp[tid] = segpos[t0 + tid];
    cp_commit();

    float m[2]    = {-1e30f, -1e30f};
    float lsum[2] = {0.f, 0.f};
    float O[16][4];
    #pragma unroll
    for (int i = 0; i < 16; i++)
        #pragma unroll
        for (int j = 0; j < 4; j++) O[i][j] = 0.f;

    int sp0 = segpos[t0];
    int s_lo = sp0 - (WINDOW - 1); if (s_lo < 0) s_lo = 0;
    const int sb = s_lo & ~63;

    const int g8   = lane >> 2;
    const int q2   = (lane & 3) << 1;
    const int arow = (lane & 7) + ((lane & 8) ? 8 : 0);
    const int asel = (lane & 16) ? 8 : 0;
    const int krow = (lane & 7) + ((lane & 16) ? 8 : 0);
    const int ksel = (lane & 8) ? 8 : 0;
    const int vkey = lane & 15;
    const int vsel = (lane & 16) ? 8 : 0;

    const int rowt = t0 + w * 16 + g8;          // absolute t for half 0
    // (sp read below after first sync)

    for (int s0 = sb; s0 <= t0 + 63; s0 += 64) {
        #pragma unroll
        for (int i = tid; i < 1024; i += 128) {
            int r = i >> 4, c = (i & 15) << 3;
            size_t g = (size_t)(s0 + r) * (KVHEADS * HDIM) + (kvh << 7) + c;
            cp16(Kh + r * AST + c, g_Kh + g);
            cp16(Kl + r * AST + c, g_Kl + g);
            cp16(Vh + r * AST + c, g_Vh + g);
            cp16(Vl + r * AST + c, g_Vl + g);
        }
        cp_commit();
        asm volatile("cp.async.wait_group 0;\n");
        __syncthreads();

        // ---- S = Q K^T (hi/lo split, 3 MMA) ----
        float S[8][4];
        #pragma unroll
        for (int i = 0; i < 8; i++)
            #pragma unroll
            for (int j = 0; j < 4; j++) S[i][j] = 0.f;

        #pragma unroll
        for (int k16 = 0; k16 < 8; k16++) {
            uint32_t ah[4], al[4];
            int aoff = (w * 16 + arow) * AST + k16 * 16 + asel;
            ldsm4(ah[0], ah[1], ah[2], ah[3], Qh + aoff);
            ldsm4(al[0], al[1], al[2], al[3], Ql + aoff);
            #pragma unroll
            for (int nt = 0; nt < 4; nt++) {
                uint32_t bh[4], bl[4];
                int koff = (nt * 16 + krow) * AST + k16 * 16 + ksel;
                ldsm4(bh[0], bh[1], bh[2], bh[3], Kh + koff);
                ldsm4(bl[0], bl[1], bl[2], bl[3], Kl + koff);
                mma16816(S[2 * nt],     ah, bh[0], bh[1]);
                mma16816(S[2 * nt],     ah, bl[0], bl[1]);
                mma16816(S[2 * nt],     al, bh[0], bh[1]);
                mma16816(S[2 * nt + 1], ah, bh[2], bh[3]);
                mma16816(S[2 * nt + 1], ah, bl[2], bl[3]);
                mma16816(S[2 * nt + 1], al, bh[2], bh[3]);
            }
        }

        // ---- softcap + mask ----
        const int sp_r0 = sp[w * 16 + g8];
        const int sp_r1 = sp[w * 16 + g8 + 8];
        #pragma unroll
        for (int nt = 0; nt < 8; nt++) {
            int scol0 = s0 + nt * 8 + q2;
            #pragma unroll
            for (int jj = 0; jj < 4; jj++) {
                int s = scol0 + (jj & 1);
                int t = rowt + ((jj & 2) ? 8 : 0);
                int p = (jj & 2) ? sp_r1 : sp_r0;
                float x = S[nt][jj] * 0.02f;                       // s / 50
                float e = __expf(2.f * x);
                float th = 1.f - __fdividef(2.f, e + 1.f);          // tanh, inf-safe
                bool ok = (s <= t) && (s > p - WINDOW) && (s < p + WINDOW);
                S[nt][jj] = ok ? (50.f * th) : -1e30f;
            }
        }

        // ---- online softmax (per half-row) ----
        #pragma unroll
        for (int h = 0; h < 2; h++) {
            float mx = -1e30f;
            #pragma unroll
            for (int nt = 0; nt < 8; nt++)
                mx = fmaxf(mx, fmaxf(S[nt][2 * h], S[nt][2 * h + 1]));
            mx = fmaxf(mx, __shfl_xor_sync(0xffffffffu, mx, 1));
            mx = fmaxf(mx, __shfl_xor_sync(0xffffffffu, mx, 2));
            float mnew  = fmaxf(m[h], mx);
            float alpha = __expf(m[h] - mnew);
            float rs = 0.f;
            #pragma unroll
            for (int nt = 0; nt < 8; nt++) {
                #pragma unroll
                for (int e2 = 0; e2 < 2; e2++) {
                    float sv = S[nt][2 * h + e2];
                    float pv = (sv < -9e29f) ? 0.f : __expf(sv - mnew);
                    S[nt][2 * h + e2] = pv;
                    rs += pv;
                }
            }
            rs += __shfl_xor_sync(0xffffffffu, rs, 1);
            rs += __shfl_xor_sync(0xffffffffu, rs, 2);
            lsum[h] = lsum[h] * alpha + rs;
            #pragma unroll
            for (int nt = 0; nt < 16; nt++) {
                O[nt][2 * h]     *= alpha;
                O[nt][2 * h + 1] *= alpha;
            }
            m[h] = mnew;
        }

        // ---- O += P V (hi/lo split, P packed straight from accumulators) ----
        #pragma unroll
        for (int kt = 0; kt < 4; kt++) {
            uint32_t pah[4], pal[4];
            pack_split(S[2 * kt][0],     S[2 * kt][1],     pah[0], pal[0]);
            pack_split(S[2 * kt][2],     S[2 * kt][3],     pah[1], pal[1]);
            pack_split(S[2 * kt + 1][0], S[2 * kt + 1][1], pah[2], pal[2]);
            pack_split(S[2 * kt + 1][2], S[2 * kt + 1][3], pah[3], pal[3]);
            #pragma unroll
            for (int ht = 0; ht < 8; ht++) {
                uint32_t vh[4], vl[4];
                int voff = (kt * 16 + vkey) * AST + ht * 16 + vsel;
                ldsm4t(vh[0], vh[1], vh[2], vh[3], Vh + voff);
                ldsm4t(vl[0], vl[1], vl[2], vl[3], Vl + voff);
                mma16816(O[2 * ht],     pah, vh[0], vh[1]);
                mma16816(O[2 * ht],     pah, vl[0], vl[1]);
                mma16816(O[2 * ht],     pal, vh[0], vh[1]);
                mma16816(O[2 * ht + 1], pah, vh[2], vh[3]);
                mma16816(O[2 * ht + 1], pah, vl[2], vl[3]);
                mma16816(O[2 * ht + 1], pal, vh[2], vh[3]);
            }
        }
        __syncthreads();
    }

    // ---- epilogue ----
    #pragma unroll
    for (int h = 0; h < 2; h++) {
        float inv = 1.0f / lsum[h];
        int row = t0 + w * 16 + g8 + 8 * h;
        float* dst = g_Enc + (size_t)row * (NHEADS * HDIM) + (n << 7) + q2;
        #pragma unroll
        for (int nt = 0; nt < 16; nt++) {
            float2 v = make_float2(O[nt][2 * h] * inv, O[nt][2 * h + 1] * inv);
            *reinterpret_cast<float2*>(dst + nt * 8) = v;
        }
    }
}

// ---------------- launch ----------------
extern "C" void kernel_launch(void* const* d_in, const int* in_sizes, int n_in,
                              void* d_out, int out_size) {
    const float* x      = (const float*)d_in[0];
    const int*   segpos = (const int*)d_in[1];
    const float* qw   = (const float*)d_in[3];
    const float* kvw  = (const float*)d_in[4];
    const float* outw = (const float*)d_in[5];
    float* out = (float*)d_out;

    __nv_bfloat16 *pAh, *pAl, *pBqh, *pBql, *pBkh, *pBkl, *pBvh, *pBvl, *pBoh, *pBol;
    float *pQ, *pK, *pV, *pEnc;
    __nv_bfloat16 *pQh, *pQl, *pKh, *pKl;
    cudaGetSymbolAddress((void**)&pAh, g_Ah);
    cudaGetSymbolAddress((void**)&pAl, g_Al);
    cudaGetSymbolAddress((void**)&pBqh, g_Bqh);
    cudaGetSymbolAddress((void**)&pBql, g_Bql);
    cudaGetSymbolAddress((void**)&pBkh, g_Bkh);
    cudaGetSymbolAddress((void**)&pBkl, g_Bkl);
    cudaGetSymbolAddress((void**)&pBvh, g_Bvh);
    cudaGetSymbolAddress((void**)&pBvl, g_Bvl);
    cudaGetSymbolAddress((void**)&pBoh, g_Boh);
    cudaGetSymbolAddress((void**)&pBol, g_Bol);
    cudaGetSymbolAddress((void**)&pQ,  g_Q);
    cudaGetSymbolAddress((void**)&pK,  g_K);
    cudaGetSymbolAddress((void**)&pV,  g_V);
    cudaGetSymbolAddress((void**)&pEnc, g_Enc);
    cudaGetSymbolAddress((void**)&pQh, g_Qh);
    cudaGetSymbolAddress((void**)&pQl, g_Ql2);
    cudaGetSymbolAddress((void**)&pKh, g_Kh);
    cudaGetSymbolAddress((void**)&pKl, g_Kl);

    pack_convert<<<2048, 256>>>(x, qw, kvw, outw);

    const int GEMM_SMEM = 2 * STAGE_ELEMS * (int)sizeof(__nv_bfloat16);
    cudaFuncSetAttribute(gemm_bf16split, cudaFuncAttributeMaxDynamicSharedMemorySize, GEMM_SMEM);

    gemm_bf16split<<<dim3(32, 16), 256, GEMM_SMEM>>>(pAh, pAl, pBqh, pBql, pQ, T_SEQ, NHEADS * HDIM, D_MODEL);
    gemm_bf16split<<<dim3(8, 16), 256, GEMM_SMEM>>>(pAh, pAl, pBkh, pBkl, pK, T_SEQ, KVHEADS * HDIM, D_MODEL);
    gemm_bf16split<<<dim3(8, 16), 256, GEMM_SMEM>>>(pAh, pAl, pBvh, pBvl, pV, T_SEQ, KVHEADS * HDIM, D_MODEL);

    rope_split<<<(T_SEQ * NHEADS * 64 + 255) / 256, 256>>>(pQ, segpos, NHEADS, 0.08838834764831845f, pQh, pQl);
    rope_split<<<(T_SEQ * KVHEADS * 64 + 255) / 256, 256>>>(pK, segpos, KVHEADS, 1.0f, pKh, pKl);
    v_split<<<512, 256>>>();

    const int ATTN_SMEM = 6 * 64 * AST * (int)sizeof(__nv_bfloat16);  // 104448
    cudaFuncSetAttribute(attn_tc, cudaFuncAttributeMaxDynamicSharedMemorySize, ATTN_SMEM);
    attn_tc<<<dim3(NHEADS, T_SEQ / 64), 128, ATTN_SMEM>>>(segpos);

    enc_convert<<<2048, 256>>>();

    gemm_bf16split<<<dim3(32, 16), 256, GEMM_SMEM>>>(pAh, pAl, pBoh, pBol, out, T_SEQ, D_MODEL, NHEADS * HDIM);
}